// round 7
// baseline (speedup 1.0000x reference)
#include <cuda_runtime.h>
#include <cuda_bf16.h>
#include <mma.h>
using namespace nvcuda;

#define BB 16
#define CC 1024
#define PP 512
#define NN 4096
#define MM 1024
typedef __nv_bfloat16 bf16;

// ---- scratch (device globals; resolved via cudaGetSymbolAddress ONLY) ----
__device__ __align__(16) bf16  g_xb [(long)BB*CC*NN];
__device__ __align__(16) float g_ixf[(long)BB*CC*MM];
__device__ __align__(16) bf16  g_ixb[(long)BB*CC*MM];
__device__ __align__(16) bf16  g_qT [(long)BB*NN*PP];
__device__ __align__(16) bf16  g_k  [(long)BB*PP*MM];
__device__ __align__(16) bf16  g_vT [(long)BB*MM*PP];
__device__ __align__(16) float g_S  [(long)BB*NN*MM];
__device__ __align__(16) bf16  g_P  [(long)BB*NN*MM];
__device__ __align__(16) bf16  g_oT [(long)BB*NN*PP];
__device__ __align__(16) bf16  g_wqb[PP*CC];
__device__ __align__(16) bf16  g_wkb[PP*CC];
__device__ __align__(16) bf16  g_wvb[PP*CC];
__device__ __align__(16) bf16  g_woutT[PP*CC];
__device__ float g_mask[BB*MM];
__device__ float g_t[BB*CC];
__device__ float g_gc[BB*PP];
__device__ float g_gcw[BB*CC];
__device__ float g_qsum[BB*PP];
__device__ float g_dbg[16];

// ---------------- elementwise / reductions (ALL buffers passed as args) ----------------

__global__ void k_f2bf(const float* __restrict__ src, bf16* __restrict__ dst, long n4){
    long i = (long)blockIdx.x*256 + threadIdx.x;
    if (i >= n4) return;
    float4 f = ((const float4*)src)[i];
    ((__nv_bfloat162*)dst)[i*2]   = __floats2bfloat162_rn(f.x, f.y);
    ((__nv_bfloat162*)dst)[i*2+1] = __floats2bfloat162_rn(f.z, f.w);
}

__global__ void k_pool2(const float* __restrict__ x, float* __restrict__ ixf,
                        bf16* __restrict__ ixb){
    long idx = (long)blockIdx.x*256 + threadIdx.x;   // B*C*M threads
    int m = (int)(idx & (MM-1));
    long bc = idx >> 10;
    int hk = m >> 5, wk = m & 31;
    const float* base = x + bc*(long)NN + (hk*2)*64 + wk*2;
    float v = fmaxf(fmaxf(base[0], base[1]), fmaxf(base[64], base[65]));
    ixf[idx] = v;
    ixb[idx] = __float2bfloat16(v);
}

__global__ void k_wtrans(const float* __restrict__ w, bf16* __restrict__ wt){
    int idx = blockIdx.x*256 + threadIdx.x;          // P*C threads
    int p = idx >> 10, c = idx & 1023;
    wt[idx] = __float2bfloat16(w[c*PP + p]);
}

__global__ void k_zero(float* __restrict__ p){ p[blockIdx.x*256 + threadIdx.x] = 0.f; }

__global__ void k_qsum(const bf16* __restrict__ qT, float* __restrict__ qsum){
    int p = blockIdx.x*256 + threadIdx.x;            // grid (2,16,8)
    int b = blockIdx.y;
    int n0 = blockIdx.z*512;
    const bf16* base = qT + (long)b*NN*PP;
    float s = 0.f;
    for (int n=n0;n<n0+512;n++) s += __bfloat162float(base[(long)n*PP + p]);
    atomicAdd(&qsum[b*PP+p], s);
}

__global__ void k_qsub(bf16* __restrict__ qT, const float* __restrict__ qsum){
    int p = blockIdx.x*256 + threadIdx.x;            // grid (2,16,16)
    int b = blockIdx.y;
    int n0 = blockIdx.z*256;
    float mean = qsum[b*PP+p] * (1.f/NN);
    bf16* base = qT + (long)b*NN*PP;
    for (int n=n0;n<n0+256;n++){
        long o = (long)n*PP + p;
        base[o] = __float2bfloat16(__bfloat162float(base[o]) - mean);
    }
}

__global__ void k_meansub_k(bf16* __restrict__ kM){  // grid (512,16), block 256
    int p = blockIdx.x, b = blockIdx.y, tid = threadIdx.x;
    bf16* row = kM + ((long)b*PP + p)*MM;
    float s = 0.f;
    for (int m=tid;m<MM;m+=256) s += __bfloat162float(row[m]);
    __shared__ float red[256];
    red[tid]=s; __syncthreads();
    for (int st=128;st;st>>=1){ if (tid<st) red[tid]+=red[tid+st]; __syncthreads(); }
    float mean = red[0] * (1.f/MM);
    for (int m=tid;m<MM;m+=256) row[m] = __float2bfloat16(__bfloat162float(row[m]) - mean);
}

__global__ void k_softmax(const float* __restrict__ S, bf16* __restrict__ P){
    long r = blockIdx.x;                             // grid B*N, block 128
    const float* src = S + r*MM;
    bf16* dst = P + r*MM;
    int tid = threadIdx.x;
    __shared__ float red[128];
    float mx = -1e30f;
    #pragma unroll
    for (int i=0;i<8;i++) mx = fmaxf(mx, src[tid + i*128]);
    red[tid]=mx; __syncthreads();
    for (int st=64;st;st>>=1){ if (tid<st) red[tid]=fmaxf(red[tid],red[tid+st]); __syncthreads(); }
    mx = red[0]; __syncthreads();
    float e[8]; float s = 0.f;
    #pragma unroll
    for (int i=0;i<8;i++){ e[i] = __expf(src[tid + i*128] - mx); s += e[i]; }
    red[tid]=s; __syncthreads();
    for (int st=64;st;st>>=1){ if (tid<st) red[tid]+=red[tid+st]; __syncthreads(); }
    float rinv = 1.f/red[0];
    #pragma unroll
    for (int i=0;i<8;i++) dst[tid + i*128] = __float2bfloat16(e[i]*rinv);
}

// ---- f32 global-context branch ----
__global__ void k_masklogit(const float* __restrict__ ixf, const float* __restrict__ wmask,
                            const float* __restrict__ bmask, float* __restrict__ mask){
    int m = blockIdx.x*256 + threadIdx.x;            // grid (4,16)
    int b = blockIdx.y;
    const float* ix = ixf + (long)b*CC*MM;
    float s = bmask[0];
    for (int c=0;c<CC;c++) s += wmask[c]*ix[(long)c*MM + m];
    mask[b*MM+m] = s;
}

__global__ void k_masksoftmax(float* __restrict__ mask){  // grid (16), block 256
    int b = blockIdx.x; int tid = threadIdx.x;
    float* row = mask + b*MM;
    __shared__ float red[256];
    float mx = -1e30f;
    for (int m=tid;m<MM;m+=256) mx = fmaxf(mx, row[m]);
    red[tid]=mx; __syncthreads();
    for (int st=128;st;st>>=1){ if (tid<st) red[tid]=fmaxf(red[tid],red[tid+st]); __syncthreads(); }
    mx = red[0]; __syncthreads();
    float s = 0.f;
    for (int m=tid;m<MM;m+=256){ float e = __expf(row[m]-mx); row[m]=e; s+=e; }
    red[tid]=s; __syncthreads();
    for (int st=128;st;st>>=1){ if (tid<st) red[tid]+=red[tid+st]; __syncthreads(); }
    float rinv = 1.f/red[0];
    for (int m=tid;m<MM;m+=256) row[m] *= rinv;
}

__global__ void k_t(const float* __restrict__ ixf, const float* __restrict__ mask,
                    float* __restrict__ t){          // grid (1024,16), block 128
    int c = blockIdx.x, b = blockIdx.y, tid = threadIdx.x;
    const float* ix = ixf + ((long)b*CC + c)*MM;
    float s = 0.f;
    for (int m=tid;m<MM;m+=128) s += ix[m]*mask[b*MM+m];
    __shared__ float red[128];
    red[tid]=s; __syncthreads();
    for (int st=64;st;st>>=1){ if (tid<st) red[tid]+=red[tid+st]; __syncthreads(); }
    if (tid==0) t[b*CC+c] = red[0];
}

__global__ void k_gc(const float* __restrict__ wgc, const float* __restrict__ bgc,
                     const float* __restrict__ t, float* __restrict__ gc){
    int p = blockIdx.x, b = blockIdx.y, tid = threadIdx.x;   // grid (512,16), block 256
    float s = 0.f;
    for (int c=tid;c<CC;c+=256) s += wgc[p*CC+c]*t[b*CC+c];
    __shared__ float red[256];
    red[tid]=s; __syncthreads();
    for (int st=128;st;st>>=1){ if (tid<st) red[tid]+=red[tid+st]; __syncthreads(); }
    if (tid==0) gc[b*PP+p] = red[0] + bgc[p];
}

__global__ void k_gcw(const float* __restrict__ wout, const float* __restrict__ beta,
                      const float* __restrict__ gc, float* __restrict__ gcw){
    int c = blockIdx.x, b = blockIdx.y, tid = threadIdx.x;   // grid (1024,16), block 128
    float s = 0.f;
    for (int p=tid;p<PP;p+=128) s += wout[c*PP+p]*gc[b*PP+p];
    __shared__ float red[128];
    red[tid]=s; __syncthreads();
    for (int st=64;st;st>>=1){ if (tid<st) red[tid]+=red[tid+st]; __syncthreads(); }
    if (tid==0) gcw[b*CC+c] = beta[0]*red[0];
}

// ---- generic bf16 wmma GEMM: C = A[M,K] @ B[K,N], 128x128 tile, 8 warps ----
// MODE 0: bf16 Out[m*Ndim+n] = acc + bias[m]
// MODE 1: bf16 Out[n*Mdim+m] = acc + bias[m]
// MODE 2: f32  Out[n*Mdim+m] = xres + gamma[0]*acc + gcw[b*CC+n]
// MODE 3: f32  Out[m*Ndim+n] = acc * hscale
// MODE 4: bf16 Out[m*Ndim+n] = acc
struct SmemLd { bf16 As[128*48]; bf16 Bs[32*144]; };
union SmemU { SmemLd ld; float stage[64*136]; };

template<int MODE>
__global__ void __launch_bounds__(256)
gemm_kernel(const bf16* __restrict__ A, const bf16* __restrict__ Bmat,
            const float* __restrict__ bias, void* __restrict__ OutV,
            int Mdim, int Ndim, int Kdim, long sA, long sB, long sOut,
            const float* __restrict__ xres, const float* __restrict__ gcw,
            const float* __restrict__ gamma, float hscale)
{
    __shared__ __align__(16) SmemU sm;
    const int b = blockIdx.z;
    A    += (long)b * sA;
    Bmat += (long)b * sB;
    const int m0 = blockIdx.y * 128;
    const int n0 = blockIdx.x * 128;
    const int tid = threadIdx.x;
    const int wid = tid >> 5;
    const int warp_m = wid >> 2;
    const int warp_n = wid & 3;

    wmma::fragment<wmma::accumulator,16,16,16,float> acc[4][2];
    #pragma unroll
    for (int i=0;i<4;i++)
        #pragma unroll
        for (int j=0;j<2;j++) wmma::fill_fragment(acc[i][j], 0.f);

    for (int k0 = 0; k0 < Kdim; k0 += 32) {
        #pragma unroll
        for (int p=0;p<2;p++){
            int v = tid + p*256;
            int r = v >> 2, c8 = v & 3;
            *(uint4*)(&sm.ld.As[r*48 + c8*8]) =
              *(const uint4*)(&A[(long)(m0+r)*Kdim + k0 + c8*8]);
        }
        #pragma unroll
        for (int p=0;p<2;p++){
            int v = tid + p*256;
            int r = v >> 4, c8 = v & 15;
            *(uint4*)(&sm.ld.Bs[r*144 + c8*8]) =
              *(const uint4*)(&Bmat[(long)(k0+r)*Ndim + n0 + c8*8]);
        }
        __syncthreads();
        #pragma unroll
        for (int kk=0; kk<32; kk+=16){
            wmma::fragment<wmma::matrix_a,16,16,16,bf16,wmma::row_major> af[4];
            wmma::fragment<wmma::matrix_b,16,16,16,bf16,wmma::row_major> bfr[2];
            #pragma unroll
            for (int i=0;i<4;i++)
                wmma::load_matrix_sync(af[i], &sm.ld.As[(warp_m*64 + i*16)*48 + kk], 48);
            #pragma unroll
            for (int j=0;j<2;j++)
                wmma::load_matrix_sync(bfr[j], &sm.ld.Bs[kk*144 + warp_n*32 + j*16], 144);
            #pragma unroll
            for (int i=0;i<4;i++)
                #pragma unroll
                for (int j=0;j<2;j++)
                    wmma::mma_sync(acc[i][j], af[i], bfr[j], acc[i][j]);
        }
        __syncthreads();
    }

    const float gmul = (MODE==2) ? gamma[0] : 0.f;
    for (int h=0; h<2; h++){
        if (warp_m == h){
            #pragma unroll
            for (int i=0;i<4;i++)
                #pragma unroll
                for (int j=0;j<2;j++)
                    wmma::store_matrix_sync(&sm.stage[(i*16)*136 + warp_n*32 + j*16],
                                            acc[i][j], 136, wmma::mem_row_major);
        }
        __syncthreads();
        if (MODE == 0 || MODE == 4){
            bf16* Out = (bf16*)OutV + (long)b*sOut;
            for (int it=0; it<32; it++){
                int idx = it*256 + tid;
                int r = idx >> 7, c = idx & 127;
                int gmi = m0 + h*64 + r, gni = n0 + c;
                float v = sm.stage[r*136 + c] + ((MODE==0) ? bias[gmi] : 0.f);
                Out[(long)gmi*Ndim + gni] = __float2bfloat16(v);
            }
        } else if (MODE == 1){
            bf16* Out = (bf16*)OutV + (long)b*sOut;
            for (int it=0; it<32; it++){
                int idx = it*256 + tid;
                int r = idx & 63, c = idx >> 6;
                int gmi = m0 + h*64 + r, gni = n0 + c;
                Out[(long)gni*Mdim + gmi] = __float2bfloat16(sm.stage[r*136 + c] + bias[gmi]);
            }
        } else if (MODE == 2){
            float* Out = (float*)OutV + (long)b*sOut;
            const float* xr = xres + (long)b*sOut;
            for (int it=0; it<32; it++){
                int idx = it*256 + tid;
                int r = idx & 63, c = idx >> 6;
                int gmi = m0 + h*64 + r;
                int gni = n0 + c;
                long o = (long)gni*Mdim + gmi;
                Out[o] = xr[o] + gmul*sm.stage[r*136 + c] + gcw[b*CC + gni];
            }
        } else {
            float* Out = (float*)OutV + (long)b*sOut;
            for (int it=0; it<32; it++){
                int idx = it*256 + tid;
                int r = idx >> 7, c = idx & 127;
                int gmi = m0 + h*64 + r, gni = n0 + c;
                Out[(long)gmi*Ndim + gni] = sm.stage[r*136 + c] * hscale;
            }
        }
        __syncthreads();
    }
}

// ---------------- probes + canary (consistent pointers) ----------------
__global__ void k_probe_f32(const float* __restrict__ p, long stride, int idx,
                            float* __restrict__ dbg){
    int tid = threadIdx.x;
    float s = 0.f;
    for (int i=tid;i<1024;i+=256) s += fabsf(p[(long)i*stride]);
    __shared__ float red[256];
    red[tid]=s; __syncthreads();
    for (int st=128;st;st>>=1){ if (tid<st) red[tid]+=red[tid+st]; __syncthreads(); }
    if (tid==0) dbg[idx] = red[0];
}

__global__ void k_probe_bf16(const bf16* __restrict__ p, long stride, int idx,
                             float* __restrict__ dbg){
    int tid = threadIdx.x;
    float s = 0.f;
    for (int i=tid;i<1024;i+=256) s += fabsf(__bfloat162float(p[(long)i*stride]));
    __shared__ float red[256];
    red[tid]=s; __syncthreads();
    for (int st=128;st;st>>=1){ if (tid<st) red[tid]+=red[tid+st]; __syncthreads(); }
    if (tid==0) dbg[idx] = red[0];
}

__global__ void k_canary(float* out, int errbits, const float* __restrict__ dbg){
    long dead = 0;
    for (int i=0;i<8;i++) if (dbg[i] == 0.f) dead |= (1L<<i);
    double add = (double)errbits*1e4 + (double)dead*1e8;
    if (add != 0.0) out[0] = (float)add;
}

extern "C" void kernel_launch(void* const* d_in, const int* in_sizes, int n_in,
                              void* d_out, int out_size) {
    const float* x     = (const float*)d_in[0];
    const float* wq    = (const float*)d_in[1];
    const float* bq    = (const float*)d_in[2];
    const float* wk    = (const float*)d_in[3];
    const float* bk    = (const float*)d_in[4];
    const float* wv    = (const float*)d_in[5];
    const float* bv    = (const float*)d_in[6];
    const float* wgc   = (const float*)d_in[7];
    const float* bgc   = (const float*)d_in[8];
    const float* wmask = (const float*)d_in[9];
    const float* bmask = (const float*)d_in[10];
    const float* wout  = (const float*)d_in[11];
    const float* gamma = (const float*)d_in[12];
    const float* beta  = (const float*)d_in[13];
    float* out = (float*)d_out;

    // --- resolve EVERY device-global through the runtime (host shadows are poison) ---
    int errbits = 0;
    void *p_xb, *p_ixf, *p_ixb, *p_qT, *p_k, *p_vT, *p_S, *p_P, *p_oT;
    void *p_wqb, *p_wkb, *p_wvb, *p_woutT, *p_mask, *p_t, *p_gc, *p_gcw, *p_qsum, *p_dbg;
    cudaError_t e = cudaSuccess;
    e = (cudaError_t)(e | cudaGetSymbolAddress(&p_xb,  g_xb));
    e = (cudaError_t)(e | cudaGetSymbolAddress(&p_ixf, g_ixf));
    e = (cudaError_t)(e | cudaGetSymbolAddress(&p_ixb, g_ixb));
    e = (cudaError_t)(e | cudaGetSymbolAddress(&p_qT,  g_qT));
    e = (cudaError_t)(e | cudaGetSymbolAddress(&p_k,   g_k));
    e = (cudaError_t)(e | cudaGetSymbolAddress(&p_vT,  g_vT));
    e = (cudaError_t)(e | cudaGetSymbolAddress(&p_S,   g_S));
    e = (cudaError_t)(e | cudaGetSymbolAddress(&p_P,   g_P));
    e = (cudaError_t)(e | cudaGetSymbolAddress(&p_oT,  g_oT));
    e = (cudaError_t)(e | cudaGetSymbolAddress(&p_wqb, g_wqb));
    e = (cudaError_t)(e | cudaGetSymbolAddress(&p_wkb, g_wkb));
    e = (cudaError_t)(e | cudaGetSymbolAddress(&p_wvb, g_wvb));
    e = (cudaError_t)(e | cudaGetSymbolAddress(&p_woutT, g_woutT));
    e = (cudaError_t)(e | cudaGetSymbolAddress(&p_mask, g_mask));
    e = (cudaError_t)(e | cudaGetSymbolAddress(&p_t,   g_t));
    e = (cudaError_t)(e | cudaGetSymbolAddress(&p_gc,  g_gc));
    e = (cudaError_t)(e | cudaGetSymbolAddress(&p_gcw, g_gcw));
    e = (cudaError_t)(e | cudaGetSymbolAddress(&p_qsum, g_qsum));
    e = (cudaError_t)(e | cudaGetSymbolAddress(&p_dbg, g_dbg));
    if (e != cudaSuccess) errbits |= 1<<8;

    const float SINV = 0.8838834764831844f;  // 1/(sqrt(512)*0.05)
    cudaGetLastError();  // clear

    // conversions + pooling
    k_f2bf<<<65536, 256>>>(x, (bf16*)p_xb, (long)BB*CC*NN/4);
    k_pool2<<<65536, 256>>>(x, (float*)p_ixf, (bf16*)p_ixb);
    if (cudaGetLastError() != cudaSuccess) errbits |= 1<<0;
    k_probe_f32<<<1,256>>>((const float*)p_ixf, 16384, 0, (float*)p_dbg);
    k_f2bf<<<512, 256>>>(wq, (bf16*)p_wqb, PP*CC/4);
    k_f2bf<<<512, 256>>>(wk, (bf16*)p_wkb, PP*CC/4);
    k_f2bf<<<512, 256>>>(wv, (bf16*)p_wvb, PP*CC/4);
    k_wtrans<<<2048, 256>>>(wout, (bf16*)p_woutT);

    // q = wq@x + bq -> qT [b][n][p]; whiten over n
    gemm_kernel<1><<<dim3(32,4,16), 256>>>((const bf16*)p_wqb, (const bf16*)p_xb, bq, p_qT,
        PP, NN, CC, 0, (long)CC*NN, (long)NN*PP, nullptr, nullptr, nullptr, 0.f);
    if (cudaGetLastError() != cudaSuccess) errbits |= 1<<1;
    k_zero<<<32, 256>>>((float*)p_qsum);
    k_qsum<<<dim3(2,16,8), 256>>>((const bf16*)p_qT, (float*)p_qsum);
    k_qsub<<<dim3(2,16,16), 256>>>((bf16*)p_qT, (const float*)p_qsum);
    k_probe_bf16<<<1,256>>>((const bf16*)p_qT, 32768, 1, (float*)p_dbg);

    // k = wk@ix + bk -> k [b][p][m]; whiten over m
    gemm_kernel<0><<<dim3(8,4,16), 256>>>((const bf16*)p_wkb, (const bf16*)p_ixb, bk, p_k,
        PP, MM, CC, 0, (long)CC*MM, (long)PP*MM, nullptr, nullptr, nullptr, 0.f);
    if (cudaGetLastError() != cudaSuccess) errbits |= 1<<2;
    k_meansub_k<<<dim3(512,16), 256>>>((bf16*)p_k);
    k_probe_bf16<<<1,256>>>((const bf16*)p_k, 16384, 2, (float*)p_dbg);

    // v = wv@ix + bv -> vT [b][m][p]
    gemm_kernel<1><<<dim3(8,4,16), 256>>>((const bf16*)p_wvb, (const bf16*)p_ixb, bv, p_vT,
        PP, MM, CC, 0, (long)CC*MM, (long)MM*PP, nullptr, nullptr, nullptr, 0.f);
    if (cudaGetLastError() != cudaSuccess) errbits |= 1<<3;
    k_probe_bf16<<<1,256>>>((const bf16*)p_vT, 16384, 3, (float*)p_dbg);

    // S = (qT @ k) * SINV -> f32 [b][n][m]
    gemm_kernel<3><<<dim3(8,32,16), 256>>>((const bf16*)p_qT, (const bf16*)p_k, nullptr, p_S,
        NN, MM, PP, (long)NN*PP, (long)PP*MM, (long)NN*MM, nullptr, nullptr, nullptr, SINV);
    if (cudaGetLastError() != cudaSuccess) errbits |= 1<<4;
    k_probe_f32<<<1,256>>>((const float*)p_S, 65536, 4, (float*)p_dbg);

    // softmax -> P bf16
    k_softmax<<<BB*NN, 128>>>((const float*)p_S, (bf16*)p_P);
    if (cudaGetLastError() != cudaSuccess) errbits |= 1<<5;
    k_probe_bf16<<<1,256>>>((const bf16*)p_P, 65536, 5, (float*)p_dbg);

    // O = P @ vT -> oT bf16 [b][n][p]
    gemm_kernel<4><<<dim3(4,32,16), 256>>>((const bf16*)p_P, (const bf16*)p_vT, nullptr, p_oT,
        NN, PP, MM, (long)NN*MM, (long)MM*PP, (long)NN*PP, nullptr, nullptr, nullptr, 0.f);
    if (cudaGetLastError() != cudaSuccess) errbits |= 1<<6;
    k_probe_bf16<<<1,256>>>((const bf16*)p_oT, 32768, 6, (float*)p_dbg);

    // global-context branch (vgc conv eliminated: gc = wgc@(ix@mask)+bgc)
    k_masklogit<<<dim3(4,16), 256>>>((const float*)p_ixf, wmask, bmask, (float*)p_mask);
    k_masksoftmax<<<16, 256>>>((float*)p_mask);
    k_t<<<dim3(1024,16), 128>>>((const float*)p_ixf, (const float*)p_mask, (float*)p_t);
    k_gc<<<dim3(512,16), 256>>>(wgc, bgc, (const float*)p_t, (float*)p_gc);
    k_gcw<<<dim3(1024,16), 128>>>(wout, beta, (const float*)p_gc, (float*)p_gcw);
    k_probe_f32<<<1,256>>>((const float*)p_gcw, 16, 7, (float*)p_dbg);

    // out[b][c][n] = x + gamma*(oT @ woutT)^T + gcw
    gemm_kernel<2><<<dim3(8,32,16), 256>>>((const bf16*)p_oT, (const bf16*)p_woutT, nullptr, d_out,
        NN, CC, PP, (long)NN*PP, 0, (long)CC*NN, x, (const float*)p_gcw, gamma, 0.f);
    if (cudaGetLastError() != cudaSuccess) errbits |= 1<<7;

    // silent when healthy; encodes failures into out[0] otherwise
    k_canary<<<1,1>>>(out, errbits, (const float*)p_dbg);
}

// round 9
// speedup vs baseline: 1.3007x; 1.3007x over previous
#include <cuda_runtime.h>
#include <cuda_bf16.h>
#include <cstdint>
#include <mma.h>
using namespace nvcuda;

#define BB 16
#define CC 1024
#define PP 512
#define NN 4096
#define MM 1024
typedef __nv_bfloat16 bf16;

// ---- scratch (device globals; ALWAYS resolved via cudaGetSymbolAddress) ----
__device__ __align__(16) bf16  g_xb [(long)BB*CC*NN];
__device__ __align__(16) float g_ixf[(long)BB*CC*MM];
__device__ __align__(16) bf16  g_ixb[(long)BB*CC*MM];
__device__ __align__(16) bf16  g_qT [(long)BB*NN*PP];
__device__ __align__(16) bf16  g_k  [(long)BB*PP*MM];
__device__ __align__(16) bf16  g_vT [(long)BB*MM*PP];
__device__ __align__(16) float g_S  [(long)BB*NN*MM];
__device__ __align__(16) bf16  g_P  [(long)BB*NN*MM];
__device__ __align__(16) bf16  g_oT [(long)BB*NN*PP];
__device__ __align__(16) bf16  g_wqb[PP*CC];
__device__ __align__(16) bf16  g_wkb[PP*CC];
__device__ __align__(16) bf16  g_wvb[PP*CC];
__device__ __align__(16) bf16  g_woutT[PP*CC];
__device__ float g_xsum [BB*CC];
__device__ float g_ixsum[BB*CC];
__device__ float g_qmn[BB*PP];
__device__ float g_kmn[BB*PP];
__device__ float g_mask[BB*MM];
__device__ float g_t[BB*CC];
__device__ float g_gc[BB*PP];
__device__ float g_gcw[BB*CC];

// ---------------- elementwise / reductions ----------------

__global__ void k_f2bf(const float* __restrict__ src, bf16* __restrict__ dst, long n4){
    long i = (long)blockIdx.x*256 + threadIdx.x;
    if (i >= n4) return;
    float4 f = ((const float4*)src)[i];
    ((__nv_bfloat162*)dst)[i*2]   = __floats2bfloat162_rn(f.x, f.y);
    ((__nv_bfloat162*)dst)[i*2+1] = __floats2bfloat162_rn(f.z, f.w);
}

__global__ void k_zero2(float* __restrict__ a, float* __restrict__ b){
    int idx = blockIdx.x*256 + threadIdx.x;          // grid 128: 64 blocks each
    if (blockIdx.x < 64) a[idx] = 0.f;
    else b[idx - 16384] = 0.f;
}

// pool + accumulate per-(b,c) sums of x (over n) and pooled ix (over m)
__global__ void k_pool2(const float* __restrict__ x, float* __restrict__ ixf,
                        bf16* __restrict__ ixb, float* __restrict__ xsum,
                        float* __restrict__ ixsum){
    long idx = (long)blockIdx.x*256 + threadIdx.x;   // B*C*M threads; block shares (b,c)
    int m = (int)(idx & (MM-1));
    long bc = idx >> 10;
    int hk = m >> 5, wk = m & 31;
    const float* base = x + bc*(long)NN + (hk*2)*64 + wk*2;
    float a = base[0], bq = base[1], c = base[64], d = base[65];
    float v = fmaxf(fmaxf(a, bq), fmaxf(c, d));
    ixf[idx] = v;
    ixb[idx] = __float2bfloat16(v);
    float s4 = (a + bq) + (c + d);
    __shared__ float r1[256], r2[256];
    int tid = threadIdx.x;
    r1[tid] = s4; r2[tid] = v; __syncthreads();
    for (int st=128; st; st>>=1){
        if (tid < st){ r1[tid]+=r1[tid+st]; r2[tid]+=r2[tid+st]; }
        __syncthreads();
    }
    if (tid == 0){ atomicAdd(&xsum[bc], r1[0]); atomicAdd(&ixsum[bc], r2[0]); }
}

// qmn[b][p] = (wq @ xsum_b)/NN ; kmn[b][p] = (wk @ ixsum_b)/MM   (bias cancels in whitening)
__global__ void k_means(const float* __restrict__ wq, const float* __restrict__ wk,
                        const float* __restrict__ xsum, const float* __restrict__ ixsum,
                        float* __restrict__ qmn, float* __restrict__ kmn){
    int p = blockIdx.x, b = blockIdx.y, tid = threadIdx.x;   // grid (512,16), block 256
    const float* xs = xsum + b*CC;
    const float* is = ixsum + b*CC;
    float sq = 0.f, sk = 0.f;
    for (int c=tid; c<CC; c+=256){
        sq += wq[p*CC+c]*xs[c];
        sk += wk[p*CC+c]*is[c];
    }
    __shared__ float r1[256], r2[256];
    r1[tid]=sq; r2[tid]=sk; __syncthreads();
    for (int st=128; st; st>>=1){
        if (tid<st){ r1[tid]+=r1[tid+st]; r2[tid]+=r2[tid+st]; }
        __syncthreads();
    }
    if (tid==0){ qmn[b*PP+p] = r1[0]*(1.f/NN); kmn[b*PP+p] = r2[0]*(1.f/MM); }
}

__global__ void k_wtrans(const float* __restrict__ w, bf16* __restrict__ wt){
    int idx = blockIdx.x*256 + threadIdx.x;          // P*C threads
    int p = idx >> 10, c = idx & 1023;
    wt[idx] = __float2bfloat16(w[c*PP + p]);
}

__global__ void k_softmax(const float* __restrict__ S, bf16* __restrict__ P){
    long r = blockIdx.x;                             // grid B*N, block 128
    const float* src = S + r*MM;
    bf16* dst = P + r*MM;
    int tid = threadIdx.x;
    __shared__ float red[128];
    float mx = -1e30f;
    #pragma unroll
    for (int i=0;i<8;i++) mx = fmaxf(mx, src[tid + i*128]);
    red[tid]=mx; __syncthreads();
    for (int st=64;st;st>>=1){ if (tid<st) red[tid]=fmaxf(red[tid],red[tid+st]); __syncthreads(); }
    mx = red[0]; __syncthreads();
    float e[8]; float s = 0.f;
    #pragma unroll
    for (int i=0;i<8;i++){ e[i] = __expf(src[tid + i*128] - mx); s += e[i]; }
    red[tid]=s; __syncthreads();
    for (int st=64;st;st>>=1){ if (tid<st) red[tid]+=red[tid+st]; __syncthreads(); }
    float rinv = 1.f/red[0];
    #pragma unroll
    for (int i=0;i<8;i++) dst[tid + i*128] = __float2bfloat16(e[i]*rinv);
}

// ---- f32 global-context branch ----
__global__ void k_masklogit(const float* __restrict__ ixf, const float* __restrict__ wmask,
                            const float* __restrict__ bmask, float* __restrict__ mask){
    int m = blockIdx.x*256 + threadIdx.x;            // grid (4,16)
    int b = blockIdx.y;
    const float* ix = ixf + (long)b*CC*MM;
    float s = bmask[0];
    for (int c=0;c<CC;c++) s += wmask[c]*ix[(long)c*MM + m];
    mask[b*MM+m] = s;
}

__global__ void k_masksoftmax(float* __restrict__ mask){  // grid (16), block 256
    int b = blockIdx.x; int tid = threadIdx.x;
    float* row = mask + b*MM;
    __shared__ float red[256];
    float mx = -1e30f;
    for (int m=tid;m<MM;m+=256) mx = fmaxf(mx, row[m]);
    red[tid]=mx; __syncthreads();
    for (int st=128;st;st>>=1){ if (tid<st) red[tid]=fmaxf(red[tid],red[tid+st]); __syncthreads(); }
    mx = red[0]; __syncthreads();
    float s = 0.f;
    for (int m=tid;m<MM;m+=256){ float e = __expf(row[m]-mx); row[m]=e; s+=e; }
    red[tid]=s; __syncthreads();
    for (int st=128;st;st>>=1){ if (tid<st) red[tid]+=red[tid+st]; __syncthreads(); }
    float rinv = 1.f/red[0];
    for (int m=tid;m<MM;m+=256) row[m] *= rinv;
}

__global__ void k_t(const float* __restrict__ ixf, const float* __restrict__ mask,
                    float* __restrict__ t){          // grid (1024,16), block 128
    int c = blockIdx.x, b = blockIdx.y, tid = threadIdx.x;
    const float* ix = ixf + ((long)b*CC + c)*MM;
    float s = 0.f;
    for (int m=tid;m<MM;m+=128) s += ix[m]*mask[b*MM+m];
    __shared__ float red[128];
    red[tid]=s; __syncthreads();
    for (int st=64;st;st>>=1){ if (tid<st) red[tid]+=red[tid+st]; __syncthreads(); }
    if (tid==0) t[b*CC+c] = red[0];
}

__global__ void k_gc(const float* __restrict__ wgc, const float* __restrict__ bgc,
                     const float* __restrict__ t, float* __restrict__ gc){
    int p = blockIdx.x, b = blockIdx.y, tid = threadIdx.x;   // grid (512,16), block 256
    float s = 0.f;
    for (int c=tid;c<CC;c+=256) s += wgc[p*CC+c]*t[b*CC+c];
    __shared__ float red[256];
    red[tid]=s; __syncthreads();
    for (int st=128;st;st>>=1){ if (tid<st) red[tid]+=red[tid+st]; __syncthreads(); }
    if (tid==0) gc[b*PP+p] = red[0] + bgc[p];
}

__global__ void k_gcw(const float* __restrict__ wout, const float* __restrict__ beta,
                      const float* __restrict__ gc, float* __restrict__ gcw){
    int c = blockIdx.x, b = blockIdx.y, tid = threadIdx.x;   // grid (1024,16), block 128
    float s = 0.f;
    for (int p=tid;p<PP;p+=128) s += wout[c*PP+p]*gc[b*PP+p];
    __shared__ float red[128];
    red[tid]=s; __syncthreads();
    for (int st=64;st;st>>=1){ if (tid<st) red[tid]+=red[tid+st]; __syncthreads(); }
    if (tid==0) gcw[b*CC+c] = beta[0]*red[0];
}

// ---- bf16 wmma GEMM, 128x128 tile, 8 warps, 2-stage cp.async pipeline ----
// MODE 1: bf16 Out[n*Mdim+m] = acc + bias[m]                      (v conv)
// MODE 2: f32  Out[n*Mdim+m] = xres + gamma[0]*acc + gcw[b*CC+n]  (final)
// MODE 3: f32  Out[m*Ndim+n] = acc * hscale                       (S)
// MODE 4: bf16 Out[m*Ndim+n] = acc                                (O)
// MODE 5: bf16 Out[n*Mdim+m] = acc - bias[b*PP+m]                 (q whiten)
// MODE 6: bf16 Out[m*Ndim+n] = acc - bias[b*PP+m]                 (k whiten)
#define LDA_ 40
#define LDB_ 136
struct SmemLd { bf16 A[2][128*LDA_]; bf16 B[2][32*LDB_]; };
union SmemU { SmemLd ld; float stage[64*136]; };

__device__ __forceinline__ void cp16(void* dst_smem, const void* src_gmem){
    unsigned int d = (unsigned int)__cvta_generic_to_shared(dst_smem);
    asm volatile("cp.async.cg.shared.global [%0], [%1], 16;\n" :: "r"(d), "l"(src_gmem));
}

template<int MODE>
__global__ void __launch_bounds__(256)
gemm_kernel(const bf16* __restrict__ A, const bf16* __restrict__ Bmat,
            const float* __restrict__ bias, void* __restrict__ OutV,
            int Mdim, int Ndim, int Kdim, long sA, long sB, long sOut,
            const float* __restrict__ xres, const float* __restrict__ gcw,
            const float* __restrict__ gamma, float hscale)
{
    __shared__ __align__(16) SmemU sm;
    const int b = blockIdx.z;
    A    += (long)b * sA;
    Bmat += (long)b * sB;
    const int m0 = blockIdx.y * 128;
    const int n0 = blockIdx.x * 128;
    const int tid = threadIdx.x;
    const int wid = tid >> 5;
    const int warp_m = wid >> 2;
    const int warp_n = wid & 3;

    wmma::fragment<wmma::accumulator,16,16,16,float> acc[4][2];
    #pragma unroll
    for (int i=0;i<4;i++)
        #pragma unroll
        for (int j=0;j<2;j++) wmma::fill_fragment(acc[i][j], 0.f);

    auto load_tiles = [&](int st, int k0){
        #pragma unroll
        for (int p=0;p<2;p++){
            int ch = tid + p*256;                        // A tile 128x32 = 512 16B chunks
            int r = ch >> 2, c8 = (ch & 3)*8;
            cp16(&sm.ld.A[st][r*LDA_ + c8], &A[(long)(m0+r)*Kdim + k0 + c8]);
        }
        #pragma unroll
        for (int p=0;p<2;p++){
            int ch = tid + p*256;                        // B tile 32x128 = 512 chunks
            int r = ch >> 4, c8 = (ch & 15)*8;
            cp16(&sm.ld.B[st][r*LDB_ + c8], &Bmat[(long)(k0+r)*Ndim + n0 + c8]);
        }
    };

    load_tiles(0, 0);
    asm volatile("cp.async.commit_group;\n");

    int stg = 0;
    for (int k0 = 0; k0 < Kdim; k0 += 32) {
        const bool hasnext = (k0 + 32 < Kdim);
        if (hasnext){
            load_tiles(stg^1, k0+32);
            asm volatile("cp.async.commit_group;\n");
            asm volatile("cp.async.wait_group 1;\n");
        } else {
            asm volatile("cp.async.wait_group 0;\n");
        }
        __syncthreads();
        #pragma unroll
        for (int kk=0; kk<32; kk+=16){
            wmma::fragment<wmma::matrix_a,16,16,16,bf16,wmma::row_major> af[4];
            wmma::fragment<wmma::matrix_b,16,16,16,bf16,wmma::row_major> bfr[2];
            #pragma unroll
            for (int i=0;i<4;i++)
                wmma::load_matrix_sync(af[i], &sm.ld.A[stg][(warp_m*64 + i*16)*LDA_ + kk], LDA_);
            #pragma unroll
            for (int j=0;j<2;j++)
                wmma::load_matrix_sync(bfr[j], &sm.ld.B[stg][kk*LDB_ + warp_n*32 + j*16], LDB_);
            #pragma unroll
            for (int i=0;i<4;i++)
                #pragma unroll
                for (int j=0;j<2;j++)
                    wmma::mma_sync(acc[i][j], af[i], bfr[j], acc[i][j]);
        }
        __syncthreads();
        stg ^= 1;
    }

    const float gmul = (MODE==2) ? gamma[0] : 0.f;
    for (int h=0; h<2; h++){
        if (warp_m == h){
            #pragma unroll
            for (int i=0;i<4;i++)
                #pragma unroll
                for (int j=0;j<2;j++)
                    wmma::store_matrix_sync(&sm.stage[(i*16)*136 + warp_n*32 + j*16],
                                            acc[i][j], 136, wmma::mem_row_major);
        }
        __syncthreads();
        if (MODE == 4){
            bf16* Out = (bf16*)OutV + (long)b*sOut;
            for (int it=0; it<32; it++){
                int idx = it*256 + tid;
                int r = idx >> 7, c = idx & 127;
                int gmi = m0 + h*64 + r, gni = n0 + c;
                Out[(long)gmi*Ndim + gni] = __float2bfloat16(sm.stage[r*136 + c]);
            }
        } else if (MODE == 6){
            bf16* Out = (bf16*)OutV + (long)b*sOut;
            for (int it=0; it<32; it++){
                int idx = it*256 + tid;
                int r = idx >> 7, c = idx & 127;
                int gmi = m0 + h*64 + r, gni = n0 + c;
                Out[(long)gmi*Ndim + gni] = __float2bfloat16(sm.stage[r*136 + c] - bias[b*PP + gmi]);
            }
        } else if (MODE == 1 || MODE == 5){
            bf16* Out = (bf16*)OutV + (long)b*sOut;
            for (int it=0; it<32; it++){
                int idx = it*256 + tid;
                int r = idx & 63, c = idx >> 6;
                int gmi = m0 + h*64 + r, gni = n0 + c;
                float bv = (MODE==1) ? bias[gmi] : -bias[b*PP + gmi];
                Out[(long)gni*Mdim + gmi] = __float2bfloat16(sm.stage[r*136 + c] + bv);
            }
        } else if (MODE == 2){
            float* Out = (float*)OutV + (long)b*sOut;
            const float* xr = xres + (long)b*sOut;
            for (int it=0; it<32; it++){
                int idx = it*256 + tid;
                int r = idx & 63, c = idx >> 6;
                int gmi = m0 + h*64 + r;
                int gni = n0 + c;
                long o = (long)gni*Mdim + gmi;
                Out[o] = xr[o] + gmul*sm.stage[r*136 + c] + gcw[b*CC + gni];
            }
        } else {  // MODE 3
            float* Out = (float*)OutV + (long)b*sOut;
            for (int it=0; it<32; it++){
                int idx = it*256 + tid;
                int r = idx >> 7, c = idx & 127;
                int gmi = m0 + h*64 + r, gni = n0 + c;
                Out[(long)gmi*Ndim + gni] = sm.stage[r*136 + c] * hscale;
            }
        }
        __syncthreads();
    }
}

extern "C" void kernel_launch(void* const* d_in, const int* in_sizes, int n_in,
                              void* d_out, int out_size) {
    const float* x     = (const float*)d_in[0];
    const float* wq    = (const float*)d_in[1];
    const float* wk    = (const float*)d_in[3];
    const float* wv    = (const float*)d_in[5];
    const float* bv    = (const float*)d_in[6];
    const float* wgc   = (const float*)d_in[7];
    const float* bgc   = (const float*)d_in[8];
    const float* wmask = (const float*)d_in[9];
    const float* bmask = (const float*)d_in[10];
    const float* wout  = (const float*)d_in[11];
    const float* gamma = (const float*)d_in[12];
    const float* beta  = (const float*)d_in[13];

    void *p_xb, *p_ixf, *p_ixb, *p_qT, *p_k, *p_vT, *p_S, *p_P, *p_oT;
    void *p_wqb, *p_wkb, *p_wvb, *p_woutT, *p_mask, *p_t, *p_gc, *p_gcw;
    void *p_xsum, *p_ixsum, *p_qmn, *p_kmn;
    cudaGetSymbolAddress(&p_xb,  g_xb);
    cudaGetSymbolAddress(&p_ixf, g_ixf);
    cudaGetSymbolAddress(&p_ixb, g_ixb);
    cudaGetSymbolAddress(&p_qT,  g_qT);
    cudaGetSymbolAddress(&p_k,   g_k);
    cudaGetSymbolAddress(&p_vT,  g_vT);
    cudaGetSymbolAddress(&p_S,   g_S);
    cudaGetSymbolAddress(&p_P,   g_P);
    cudaGetSymbolAddress(&p_oT,  g_oT);
    cudaGetSymbolAddress(&p_wqb, g_wqb);
    cudaGetSymbolAddress(&p_wkb, g_wkb);
    cudaGetSymbolAddress(&p_wvb, g_wvb);
    cudaGetSymbolAddress(&p_woutT, g_woutT);
    cudaGetSymbolAddress(&p_mask, g_mask);
    cudaGetSymbolAddress(&p_t,   g_t);
    cudaGetSymbolAddress(&p_gc,  g_gc);
    cudaGetSymbolAddress(&p_gcw, g_gcw);
    cudaGetSymbolAddress(&p_xsum, g_xsum);
    cudaGetSymbolAddress(&p_ixsum, g_ixsum);
    cudaGetSymbolAddress(&p_qmn, g_qmn);
    cudaGetSymbolAddress(&p_kmn, g_kmn);

    const float SINV = 0.8838834764831844f;  // 1/(sqrt(512)*0.05)

    // 1..5, then the big q GEMM is launch #6 (ncu -s 5 -c 1 profiles it)
    k_f2bf<<<65536, 256>>>(x, (bf16*)p_xb, (long)BB*CC*NN/4);                       // 1
    k_zero2<<<128, 256>>>((float*)p_xsum, (float*)p_ixsum);                         // 2
    k_pool2<<<65536, 256>>>(x, (float*)p_ixf, (bf16*)p_ixb,
                            (float*)p_xsum, (float*)p_ixsum);                       // 3
    k_means<<<dim3(512,16), 256>>>(wq, wk, (const float*)p_xsum,
                                   (const float*)p_ixsum, (float*)p_qmn, (float*)p_kmn); // 4
    k_f2bf<<<512, 256>>>(wq, (bf16*)p_wqb, PP*CC/4);                                // 5

    // q = whiten(wq@x) -> qT [b][n][p]                                             // 6 (profiled)
    gemm_kernel<5><<<dim3(32,4,16), 256>>>((const bf16*)p_wqb, (const bf16*)p_xb,
        (const float*)p_qmn, p_qT,
        PP, NN, CC, 0, (long)CC*NN, (long)NN*PP, nullptr, nullptr, nullptr, 0.f);

    k_f2bf<<<512, 256>>>(wk, (bf16*)p_wkb, PP*CC/4);
    // k = whiten(wk@ix) -> k [b][p][m]
    gemm_kernel<6><<<dim3(8,4,16), 256>>>((const bf16*)p_wkb, (const bf16*)p_ixb,
        (const float*)p_kmn, p_k,
        PP, MM, CC, 0, (long)CC*MM, (long)PP*MM, nullptr, nullptr, nullptr, 0.f);

    k_f2bf<<<512, 256>>>(wv, (bf16*)p_wvb, PP*CC/4);
    // v = wv@ix + bv -> vT [b][m][p]
    gemm_kernel<1><<<dim3(8,4,16), 256>>>((const bf16*)p_wvb, (const bf16*)p_ixb, bv, p_vT,
        PP, MM, CC, 0, (long)CC*MM, (long)MM*PP, nullptr, nullptr, nullptr, 0.f);

    // S = (qT @ k) * SINV -> f32 [b][n][m]
    gemm_kernel<3><<<dim3(8,32,16), 256>>>((const bf16*)p_qT, (const bf16*)p_k, nullptr, p_S,
        NN, MM, PP, (long)NN*PP, (long)PP*MM, (long)NN*MM, nullptr, nullptr, nullptr, SINV);

    // softmax -> P bf16
    k_softmax<<<BB*NN, 128>>>((const float*)p_S, (bf16*)p_P);

    // O = P @ vT -> oT bf16 [b][n][p]
    gemm_kernel<4><<<dim3(4,32,16), 256>>>((const bf16*)p_P, (const bf16*)p_vT, nullptr, p_oT,
        NN, PP, MM, (long)NN*MM, (long)MM*PP, (long)NN*PP, nullptr, nullptr, nullptr, 0.f);

    // global-context branch (vgc conv eliminated: gc = wgc@(ix@mask)+bgc)
    k_masklogit<<<dim3(4,16), 256>>>((const float*)p_ixf, wmask, bmask, (float*)p_mask);
    k_masksoftmax<<<16, 256>>>((float*)p_mask);
    k_t<<<dim3(1024,16), 128>>>((const float*)p_ixf, (const float*)p_mask, (float*)p_t);
    k_gc<<<dim3(512,16), 256>>>(wgc, bgc, (const float*)p_t, (float*)p_gc);
    k_gcw<<<dim3(1024,16), 128>>>(wout, beta, (const float*)p_gc, (float*)p_gcw);
    k_wtrans<<<2048, 256>>>(wout, (bf16*)p_woutT);

    // out[b][c][n] = x + gamma*(oT @ woutT)^T + gcw
    gemm_kernel<2><<<dim3(8,32,16), 256>>>((const bf16*)p_oT, (const bf16*)p_woutT, nullptr, d_out,
        NN, CC, PP, (long)NN*PP, 0, (long)CC*NN, x, (const float*)p_gcw, gamma, 0.f);
}